// round 6
// baseline (speedup 1.0000x reference)
#include <cuda_runtime.h>

// Problem constants
#define BB 2
#define CC 64
#define HH 64
#define WW 128
#define HWN (HH*WW)         // 8192
#define NXG 512
#define NYG 512
#define NCELL (NXG*NYG)     // 262144
#define SCH 4               // near-chunk slots (dynamic count may use fewer)
#define NCHUNK 2048
#define POS_INF (3.402823466e38f)

// Scratch (device globals — no runtime allocation allowed)
__device__ float  g_fvT[BB*HWN*CC];          // transposed features (B, HW, C)
__device__ float4 g_nearc[BB*HWN];           // compacted valid near pts {x,y,z,|n|^2}
__device__ int    g_near_idx[BB*HWN];        // original index of compacted near pts
__device__ int    g_near_cnt[BB];
__device__ int    g_far_idx[BB*HWN];         // compacted valid+in-range far point indices
__device__ int    g_far_cnt[BB];
__device__ float  g_part_s[BB*SCH*3*HWN];    // partial top-3 d2 [b][chunk][k][slot]
__device__ int    g_part_i[BB*SCH*3*HWN];    // partial top-3 compacted indices
__device__ float4 g_fw[BB*HWN];              // per-far-point weights {w0,w1,w2,-}
__device__ int4   g_fi[BB*HWN];              // per-far-point {i0,i1,i2,cell} (orig indices)
__device__ float  g_cnt[BB*NCELL];           // per-cell point counts

// Sorted-insert of smallest-3, strict '<' so earlier indices win ties
// (ordered compaction preserves original index order -> matches stable top_k)
#define INS(val, jj) do {                                             \
    if ((val) < s2) {                                                 \
        if ((val) < s1) {                                             \
            s2 = s1; i2 = i1;                                         \
            if ((val) < s0) { s1 = s0; i1 = i0; s0 = (val); i0 = (jj); } \
            else            { s1 = (val); i1 = (jj); }                \
        } else { s2 = (val); i2 = (jj); }                             \
    }                                                                 \
} while (0)

__device__ __forceinline__ int cell_x(float x) { return (int)floorf(__fdiv_rn(x, 0.1f)); }
__device__ __forceinline__ int cell_y(float y) { return (int)floorf(__fdiv_rn(__fsub_rn(y, -25.6f), 0.1f)); }

// |p|^2 with the reference's rounding: ((x*x + y*y) + z*z), no fma contraction
__device__ __forceinline__ float sqnorm_ref(float x, float y, float z) {
    return __fadd_rn(__fadd_rn(__fmul_rn(x, x), __fmul_rn(y, y)), __fmul_rn(z, z));
}

// GEMM-replica pair distance: acc = rn(a0*b0); acc = fma(a1,b1,acc); acc = fma(a2,b2,acc);
// d2 = rn( rn(fsq+nsq) - acc ).  Pre-doubled f is bit-equal to the alpha=2 folded GEMM.
__device__ __forceinline__ float d2_ref(float fx2, float fy2, float fz2, float fsq,
                                        float nx, float ny, float nz, float nsq) {
    float acc = __fmul_rn(fx2, nx);
    acc = __fmaf_rn(fy2, ny, acc);
    acc = __fmaf_rn(fz2, nz, acc);
    return __fsub_rn(__fadd_rn(fsq, nsq), acc);
}

// ---------------------------------------------------------------------------
// 0. transpose fv (B,C,HW) -> g_fvT (B,HW,C), smem-tiled, fully coalesced
// ---------------------------------------------------------------------------
__global__ void transpose_kernel(const float* __restrict__ fv) {
    __shared__ float tile[32][33];
    int b = blockIdx.z;
    int p0 = blockIdx.x * 32, c0 = blockIdx.y * 32;
    int tx = threadIdx.x, ty = threadIdx.y;      // 32 x 8
    #pragma unroll
    for (int i = ty; i < 32; i += 8)
        tile[i][tx] = fv[((size_t)b*CC + c0 + i) * HWN + p0 + tx];
    __syncthreads();
    #pragma unroll
    for (int i = ty; i < 32; i += 8)
        g_fvT[((size_t)b*HWN + p0 + i) * CC + c0 + tx] = tile[tx][i];
}

// ---------------------------------------------------------------------------
// 1. ordered compaction (one block per batch): valid near pts, valid+in-range far pts
// ---------------------------------------------------------------------------
__global__ void compact_kernel(const float* __restrict__ pif,
                               const int*   __restrict__ mask,
                               const float* __restrict__ piff,
                               const int*   __restrict__ maskf) {
    int b = blockIdx.x;
    int tid = threadIdx.x;                       // 256 threads, 32 elems each
    __shared__ int cnts[256], offs[256];
    int base = tid * 32;

    // --- near: predicate = mask > 0 ---
    const float* pn = pif + (size_t)b * 4 * HWN;
    const int*   mn = mask + b * HWN;
    int c = 0;
    for (int i = 0; i < 32; i++) c += (mn[base + i] > 0);
    cnts[tid] = c;
    __syncthreads();
    if (tid == 0) {
        int s = 0;
        for (int i = 0; i < 256; i++) { offs[i] = s; s += cnts[i]; }
        g_near_cnt[b] = s;
    }
    __syncthreads();
    int w = offs[tid];
    for (int i = 0; i < 32; i++) {
        int p = base + i;
        if (mn[p] > 0) {
            float x = pn[p], y = pn[HWN + p], z = pn[2*HWN + p];
            g_nearc[b*HWN + w] = make_float4(x, y, z, sqnorm_ref(x, y, z));
            g_near_idx[b*HWN + w] = p;
            w++;
        }
    }
    __syncthreads();

    // --- far: predicate = mask > 0 && cell in range ---
    const float* pff = piff + (size_t)b * 4 * HWN;
    const int*   mf  = maskf + b * HWN;
    c = 0;
    for (int i = 0; i < 32; i++) {
        int p = base + i;
        if (mf[p] > 0) {
            int ix = cell_x(pff[p]), iy = cell_y(pff[HWN + p]);
            if (ix >= 0 && ix < NXG && iy >= 0 && iy < NYG) c++;
        }
    }
    cnts[tid] = c;
    __syncthreads();
    if (tid == 0) {
        int s = 0;
        for (int i = 0; i < 256; i++) { offs[i] = s; s += cnts[i]; }
        g_far_cnt[b] = s;
    }
    __syncthreads();
    w = offs[tid];
    for (int i = 0; i < 32; i++) {
        int p = base + i;
        if (mf[p] > 0) {
            int ix = cell_x(pff[p]), iy = cell_y(pff[HWN + p]);
            if (ix >= 0 && ix < NXG && iy >= 0 && iy < NYG)
                g_far_idx[b*HWN + (w++)] = p;
        }
    }
}

// ---------------------------------------------------------------------------
// 2. near-point scatter: 64 lanes per point (4 points / 256-block)
// ---------------------------------------------------------------------------
__global__ void near_scatter_kernel(float* __restrict__ out) {
    int b = blockIdx.y;
    int slot = blockIdx.x * 4 + (threadIdx.x >> 6);
    int lane = threadIdx.x & 63;
    if (slot >= g_near_cnt[b]) return;

    float4 q = g_nearc[b*HWN + slot];            // broadcast within warp
    int ix = cell_x(q.x), iy = cell_y(q.y);
    if (ix < 0 || ix >= NXG || iy < 0 || iy >= NYG) return;
    int cell = iy * NXG + ix;
    int p = g_near_idx[b*HWN + slot];

    if (lane == 0) atomicAdd(&g_cnt[b*NCELL + cell], 1.0f);
    float f = g_fvT[((size_t)b*HWN + p) * CC + lane];           // coalesced
    atomicAdd(out + (size_t)b*CC*NCELL + (size_t)lane*NCELL + cell, f);
}

// ---------------------------------------------------------------------------
// 3. kNN over compacted near points: thread = far point, smem chunk of near pts
// ---------------------------------------------------------------------------
__global__ void __launch_bounds__(256) knn_kernel(const float* __restrict__ pif_far) {
    __shared__ float4 sh[NCHUNK];
    int b  = blockIdx.z;
    int ch = blockIdx.y;
    int nbase = ch * NCHUNK;
    int ncnt = g_near_cnt[b];
    if (nbase >= ncnt) return;
    if (blockIdx.x * 256 >= g_far_cnt[b]) return;

    int navail = min(NCHUNK, ncnt - nbase);
    int n4 = (navail + 3) & ~3;                  // pad to multiple of 4
    const float4* src = g_nearc + b*HWN + nbase;
    for (int i = threadIdx.x; i < n4; i += 256)
        sh[i] = (i < navail) ? src[i] : make_float4(0.f, 0.f, 0.f, 1e30f);
    __syncthreads();

    int slot = blockIdx.x * 256 + threadIdx.x;
    if (slot >= g_far_cnt[b]) return;
    int p = g_far_idx[b*HWN + slot];

    const float* pf = pif_far + (size_t)b * 4 * HWN;
    float x = pf[p], y = pf[HWN + p], z = pf[2*HWN + p];
    float fsq = sqnorm_ref(x, y, z);
    float fx2 = 2.0f * x, fy2 = 2.0f * y, fz2 = 2.0f * z;  // exact

    float s0 = POS_INF, s1 = POS_INF, s2 = POS_INF;
    int   i0 = 0, i1 = 0, i2 = 0;

    #pragma unroll 1
    for (int j = 0; j < n4; j += 4) {
        float4 q0 = sh[j];
        float4 q1 = sh[j+1];
        float4 q2 = sh[j+2];
        float4 q3 = sh[j+3];
        float d0  = d2_ref(fx2, fy2, fz2, fsq, q0.x, q0.y, q0.z, q0.w);
        float d1  = d2_ref(fx2, fy2, fz2, fsq, q1.x, q1.y, q1.z, q1.w);
        float d2v = d2_ref(fx2, fy2, fz2, fsq, q2.x, q2.y, q2.z, q2.w);
        float d3  = d2_ref(fx2, fy2, fz2, fsq, q3.x, q3.y, q3.z, q3.w);
        float m = fminf(fminf(d0, d1), fminf(d2v, d3));
        if (m < s2) {   // rarely taken
            INS(d0, nbase + j);
            INS(d1, nbase + j + 1);
            INS(d2v, nbase + j + 2);
            INS(d3, nbase + j + 3);
        }
    }

    int base = ((b*SCH + ch) * 3) * HWN + slot;
    g_part_s[base        ] = s0;  g_part_i[base        ] = i0;
    g_part_s[base +   HWN] = s1;  g_part_i[base +   HWN] = i1;
    g_part_s[base + 2*HWN] = s2;  g_part_i[base + 2*HWN] = i2;
}

// ---------------------------------------------------------------------------
// 4. merge partials, compute IDW weights (reference rounding), map indices,
//    compute cell; also bump the cell count
// ---------------------------------------------------------------------------
__global__ void weights_kernel(const float* __restrict__ pif_far) {
    int b = blockIdx.y;
    int slot = blockIdx.x * 256 + threadIdx.x;
    if (slot >= g_far_cnt[b]) return;
    int ncnt = g_near_cnt[b];

    float s0 = POS_INF, s1 = POS_INF, s2 = POS_INF;
    int   i0 = 0, i1 = 0, i2 = 0;
    for (int ch = 0; ch < SCH && ch*NCHUNK < ncnt; ch++) {   // skip never-run chunks
        int base = ((b*SCH + ch) * 3) * HWN + slot;
        #pragma unroll
        for (int k = 0; k < 3; k++) {
            float v = g_part_s[base + k*HWN];
            int   jj = g_part_i[base + k*HWN];
            INS(v, jj);
        }
    }

    // IDW weights exactly as reference: r = 1/(d+1e-8); w = r / ((r0+r1)+r2)
    float r0 = __fdiv_rn(1.0f, __fadd_rn(s0, 1e-8f));
    float r1 = __fdiv_rn(1.0f, __fadd_rn(s1, 1e-8f));
    float r2 = __fdiv_rn(1.0f, __fadd_rn(s2, 1e-8f));
    float rs = __fadd_rn(__fadd_rn(r0, r1), r2);
    float w0 = __fdiv_rn(r0, rs), w1 = __fdiv_rn(r1, rs), w2 = __fdiv_rn(r2, rs);

    int p = g_far_idx[b*HWN + slot];
    const float* pf = pif_far + (size_t)b * 4 * HWN;
    int ix = cell_x(pf[p]), iy = cell_y(pf[HWN + p]);   // in range by compaction
    int cell = iy * NXG + ix;

    atomicAdd(&g_cnt[b*NCELL + cell], 1.0f);
    g_fw[b*HWN + slot] = make_float4(w0, w1, w2, 0.0f);
    g_fi[b*HWN + slot] = make_int4(g_near_idx[b*HWN + i0],
                                   g_near_idx[b*HWN + i1],
                                   g_near_idx[b*HWN + i2], cell);
}

// ---------------------------------------------------------------------------
// 5. far-point scatter: 64 lanes per point, coalesced gathers from g_fvT
// ---------------------------------------------------------------------------
__global__ void far_scatter_kernel(float* __restrict__ out) {
    int b = blockIdx.y;
    int slot = blockIdx.x * 4 + (threadIdx.x >> 6);
    int lane = threadIdx.x & 63;
    if (slot >= g_far_cnt[b]) return;

    float4 w = g_fw[b*HWN + slot];
    int4  ii = g_fi[b*HWN + slot];
    const float* fT = g_fvT + (size_t)b*HWN*CC;
    // einsum order: (w0*g0 + w1*g1) + w2*g2, no fma
    float f = __fadd_rn(__fadd_rn(__fmul_rn(w.x, fT[(size_t)ii.x*CC + lane]),
                                  __fmul_rn(w.y, fT[(size_t)ii.y*CC + lane])),
                        __fmul_rn(w.z, fT[(size_t)ii.z*CC + lane]));
    atomicAdd(out + (size_t)b*CC*NCELL + (size_t)lane*NCELL + ii.w, f);
}

// ---------------------------------------------------------------------------
// 6. divide: only cells with cnt >= 2 need a fixup
// ---------------------------------------------------------------------------
__global__ void div_kernel(float* __restrict__ out) {
    int t = blockIdx.x * blockDim.x + threadIdx.x;
    if (t >= BB*NCELL) return;
    float c = g_cnt[t];
    if (c >= 2.0f) {
        int b = t / NCELL, cell = t % NCELL;
        float* ob = out + (size_t)b * CC * NCELL + cell;
        #pragma unroll 8
        for (int ch = 0; ch < CC; ch++)
            ob[(size_t)ch * NCELL] = __fdiv_rn(ob[(size_t)ch * NCELL], c);
    }
}

extern "C" void kernel_launch(void* const* d_in, const int* in_sizes, int n_in,
                              void* d_out, int out_size) {
    const float* fv    = (const float*)d_in[0];   // (B,C,H,W)
    const float* pif   = (const float*)d_in[1];   // (B,4,H,W)
    const int*   mask  = (const int*)  d_in[2];   // (B,H,W)
    const float* piff  = (const float*)d_in[3];   // (B,4,H,W)
    const int*   maskf = (const int*)  d_in[4];   // (B,H,W)
    float* out = (float*)d_out;                   // (B,C,NY,NX)

    void* p_cnt = nullptr;
    cudaGetSymbolAddress(&p_cnt, g_cnt);

    cudaMemsetAsync(d_out, 0, (size_t)BB*CC*NCELL*sizeof(float));
    cudaMemsetAsync(p_cnt, 0, (size_t)BB*NCELL*sizeof(float));

    transpose_kernel<<<dim3(HWN/32, CC/32, BB), dim3(32, 8)>>>(fv);
    compact_kernel<<<BB, 256>>>(pif, mask, piff, maskf);

    near_scatter_kernel<<<dim3(HWN/4, BB), 256>>>(out);

    knn_kernel<<<dim3(HWN/256, SCH, BB), 256>>>(piff);
    weights_kernel<<<dim3(HWN/256, BB), 256>>>(piff);
    far_scatter_kernel<<<dim3(HWN/4, BB), 256>>>(out);

    div_kernel<<<(BB*NCELL + 255)/256, 256>>>(out);
}

// round 7
// speedup vs baseline: 1.1983x; 1.1983x over previous
#include <cuda_runtime.h>

// Problem constants
#define BB 2
#define CC 64
#define HH 64
#define WW 128
#define HWN (HH*WW)         // 8192
#define NXG 512
#define NYG 512
#define NCELL (NXG*NYG)     // 262144
#define SCH 32              // near-chunk slots (dynamic count may use fewer)
#define NCHUNK 256
#define POS_INF (3.402823466e38f)

// Scratch (device globals — no runtime allocation allowed)
__device__ float  g_fvT[BB*HWN*CC];          // transposed features (B, HW, C)
__device__ float4 g_nearc[BB*HWN];           // compacted valid near pts {x,y,z,|n|^2}
__device__ int    g_near_idx[BB*HWN];        // original index of compacted near pts
__device__ int    g_near_cnt[BB];
__device__ int    g_far_idx[BB*HWN];         // compacted valid+in-range far point indices
__device__ int    g_far_cnt[BB];
__device__ float4 g_ps[BB*SCH*HWN];          // partial top-3 d2 {s0,s1,s2,-} [b][chunk][slot]
__device__ int4   g_pi[BB*SCH*HWN];          // partial top-3 compacted idx {i0,i1,i2,-}
__device__ float4 g_fw[BB*HWN];              // per-far-point weights {w0,w1,w2,-}
__device__ int4   g_fi[BB*HWN];              // per-far-point {i0,i1,i2,cell} (orig indices)
__device__ float  g_cnt[BB*NCELL];           // per-cell point counts

// Sorted-insert of smallest-3, strict '<' so earlier indices win ties
// (ordered compaction + ascending chunk order -> matches stable top_k)
#define INS(val, jj) do {                                             \
    if ((val) < s2) {                                                 \
        if ((val) < s1) {                                             \
            s2 = s1; i2 = i1;                                         \
            if ((val) < s0) { s1 = s0; i1 = i0; s0 = (val); i0 = (jj); } \
            else            { s1 = (val); i1 = (jj); }                \
        } else { s2 = (val); i2 = (jj); }                             \
    }                                                                 \
} while (0)

__device__ __forceinline__ int cell_x(float x) { return (int)floorf(__fdiv_rn(x, 0.1f)); }
__device__ __forceinline__ int cell_y(float y) { return (int)floorf(__fdiv_rn(__fsub_rn(y, -25.6f), 0.1f)); }

// |p|^2 with the reference's rounding: ((x*x + y*y) + z*z), no fma contraction
__device__ __forceinline__ float sqnorm_ref(float x, float y, float z) {
    return __fadd_rn(__fadd_rn(__fmul_rn(x, x), __fmul_rn(y, y)), __fmul_rn(z, z));
}

// GEMM-replica pair distance: acc = rn(a0*b0); acc = fma(a1,b1,acc); acc = fma(a2,b2,acc);
// d2 = rn( rn(fsq+nsq) - acc ).  Pre-doubled f is bit-equal to the alpha=2 folded GEMM.
__device__ __forceinline__ float d2_ref(float fx2, float fy2, float fz2, float fsq,
                                        float nx, float ny, float nz, float nsq) {
    float acc = __fmul_rn(fx2, nx);
    acc = __fmaf_rn(fy2, ny, acc);
    acc = __fmaf_rn(fz2, nz, acc);
    return __fsub_rn(__fadd_rn(fsq, nsq), acc);
}

// ---------------------------------------------------------------------------
// 0. transpose fv (B,C,HW) -> g_fvT (B,HW,C), smem-tiled, fully coalesced
// ---------------------------------------------------------------------------
__global__ void transpose_kernel(const float* __restrict__ fv) {
    __shared__ float tile[32][33];
    int b = blockIdx.z;
    int p0 = blockIdx.x * 32, c0 = blockIdx.y * 32;
    int tx = threadIdx.x, ty = threadIdx.y;      // 32 x 8
    #pragma unroll
    for (int i = ty; i < 32; i += 8)
        tile[i][tx] = fv[((size_t)b*CC + c0 + i) * HWN + p0 + tx];
    __syncthreads();
    #pragma unroll
    for (int i = ty; i < 32; i += 8)
        g_fvT[((size_t)b*HWN + p0 + i) * CC + c0 + tx] = tile[tx][i];
}

// ---------------------------------------------------------------------------
// 1. ordered compaction (one block per batch): valid near pts, valid+in-range far pts
// ---------------------------------------------------------------------------
__global__ void compact_kernel(const float* __restrict__ pif,
                               const int*   __restrict__ mask,
                               const float* __restrict__ piff,
                               const int*   __restrict__ maskf) {
    int b = blockIdx.x;
    int tid = threadIdx.x;                       // 256 threads, 32 elems each
    __shared__ int cnts[256], offs[256];
    int base = tid * 32;

    // --- near: predicate = mask > 0 ---
    const float* pn = pif + (size_t)b * 4 * HWN;
    const int*   mn = mask + b * HWN;
    int c = 0;
    for (int i = 0; i < 32; i++) c += (mn[base + i] > 0);
    cnts[tid] = c;
    __syncthreads();
    if (tid == 0) {
        int s = 0;
        for (int i = 0; i < 256; i++) { offs[i] = s; s += cnts[i]; }
        g_near_cnt[b] = s;
    }
    __syncthreads();
    int w = offs[tid];
    for (int i = 0; i < 32; i++) {
        int p = base + i;
        if (mn[p] > 0) {
            float x = pn[p], y = pn[HWN + p], z = pn[2*HWN + p];
            g_nearc[b*HWN + w] = make_float4(x, y, z, sqnorm_ref(x, y, z));
            g_near_idx[b*HWN + w] = p;
            w++;
        }
    }
    __syncthreads();

    // --- far: predicate = mask > 0 && cell in range ---
    const float* pff = piff + (size_t)b * 4 * HWN;
    const int*   mf  = maskf + b * HWN;
    c = 0;
    for (int i = 0; i < 32; i++) {
        int p = base + i;
        if (mf[p] > 0) {
            int ix = cell_x(pff[p]), iy = cell_y(pff[HWN + p]);
            if (ix >= 0 && ix < NXG && iy >= 0 && iy < NYG) c++;
        }
    }
    cnts[tid] = c;
    __syncthreads();
    if (tid == 0) {
        int s = 0;
        for (int i = 0; i < 256; i++) { offs[i] = s; s += cnts[i]; }
        g_far_cnt[b] = s;
    }
    __syncthreads();
    w = offs[tid];
    for (int i = 0; i < 32; i++) {
        int p = base + i;
        if (mf[p] > 0) {
            int ix = cell_x(pff[p]), iy = cell_y(pff[HWN + p]);
            if (ix >= 0 && ix < NXG && iy >= 0 && iy < NYG)
                g_far_idx[b*HWN + (w++)] = p;
        }
    }
}

// ---------------------------------------------------------------------------
// 2. kNN over compacted near points: thread = far point, small smem chunk,
//    512+ active blocks for full-chip occupancy
// ---------------------------------------------------------------------------
__global__ void __launch_bounds__(256) knn_kernel(const float* __restrict__ pif_far) {
    __shared__ float4 sh[NCHUNK];
    int b  = blockIdx.z;
    int ch = blockIdx.y;
    int nbase = ch * NCHUNK;
    int ncnt = g_near_cnt[b];
    if (nbase >= ncnt) return;
    if (blockIdx.x * 256 >= g_far_cnt[b]) return;

    int navail = min(NCHUNK, ncnt - nbase);
    int n8 = (navail + 7) & ~7;                  // pad to multiple of 8
    const float4* src = g_nearc + b*HWN + nbase;
    for (int i = threadIdx.x; i < n8; i += 256)
        sh[i] = (i < navail) ? src[i] : make_float4(0.f, 0.f, 0.f, 1e30f);
    __syncthreads();

    int slot = blockIdx.x * 256 + threadIdx.x;
    if (slot >= g_far_cnt[b]) return;
    int p = g_far_idx[b*HWN + slot];

    const float* pf = pif_far + (size_t)b * 4 * HWN;
    float x = pf[p], y = pf[HWN + p], z = pf[2*HWN + p];
    float fsq = sqnorm_ref(x, y, z);
    float fx2 = 2.0f * x, fy2 = 2.0f * y, fz2 = 2.0f * z;  // exact

    float s0 = POS_INF, s1 = POS_INF, s2 = POS_INF;
    int   i0 = 0, i1 = 0, i2 = 0;

    #pragma unroll 1
    for (int j = 0; j < n8; j += 8) {
        float d[8];
        #pragma unroll
        for (int u = 0; u < 8; u++) {
            float4 q = sh[j + u];
            d[u] = d2_ref(fx2, fy2, fz2, fsq, q.x, q.y, q.z, q.w);
        }
        float m = fminf(fminf(fminf(d[0], d[1]), fminf(d[2], d[3])),
                        fminf(fminf(d[4], d[5]), fminf(d[6], d[7])));
        if (m < s2) {   // rarely taken
            #pragma unroll
            for (int u = 0; u < 8; u++) INS(d[u], nbase + j + u);
        }
    }

    int base = (b*SCH + ch) * HWN + slot;
    g_ps[base] = make_float4(s0, s1, s2, 0.0f);
    g_pi[base] = make_int4(i0, i1, i2, 0);
}

// ---------------------------------------------------------------------------
// 3. merge partials, compute IDW weights (reference rounding), map indices,
//    compute cell; also bump the cell count
// ---------------------------------------------------------------------------
__global__ void weights_kernel(const float* __restrict__ pif_far) {
    int b = blockIdx.y;
    int slot = blockIdx.x * 256 + threadIdx.x;
    if (slot >= g_far_cnt[b]) return;
    int ncnt = g_near_cnt[b];

    float s0 = POS_INF, s1 = POS_INF, s2 = POS_INF;
    int   i0 = 0, i1 = 0, i2 = 0;
    for (int ch = 0; ch < SCH && ch*NCHUNK < ncnt; ch++) {   // skip never-run chunks
        int base = (b*SCH + ch) * HWN + slot;
        float4 v = g_ps[base];
        int4  iv = g_pi[base];
        INS(v.x, iv.x);
        INS(v.y, iv.y);
        INS(v.z, iv.z);
    }

    // IDW weights exactly as reference: r = 1/(d+1e-8); w = r / ((r0+r1)+r2)
    float r0 = __fdiv_rn(1.0f, __fadd_rn(s0, 1e-8f));
    float r1 = __fdiv_rn(1.0f, __fadd_rn(s1, 1e-8f));
    float r2 = __fdiv_rn(1.0f, __fadd_rn(s2, 1e-8f));
    float rs = __fadd_rn(__fadd_rn(r0, r1), r2);
    float w0 = __fdiv_rn(r0, rs), w1 = __fdiv_rn(r1, rs), w2 = __fdiv_rn(r2, rs);

    int p = g_far_idx[b*HWN + slot];
    const float* pf = pif_far + (size_t)b * 4 * HWN;
    int ix = cell_x(pf[p]), iy = cell_y(pf[HWN + p]);   // in range by compaction
    int cell = iy * NXG + ix;

    atomicAdd(&g_cnt[b*NCELL + cell], 1.0f);
    g_fw[b*HWN + slot] = make_float4(w0, w1, w2, 0.0f);
    g_fi[b*HWN + slot] = make_int4(g_near_idx[b*HWN + i0],
                                   g_near_idx[b*HWN + i1],
                                   g_near_idx[b*HWN + i2], cell);
}

// ---------------------------------------------------------------------------
// 4. combined scatter: blockIdx.z = 0 -> near points, 1 -> far points.
//    64 lanes per point (4 points per 256-block), coalesced g_fvT reads.
// ---------------------------------------------------------------------------
__global__ void scatter_kernel(float* __restrict__ out) {
    int b = blockIdx.y;
    int slot = blockIdx.x * 4 + (threadIdx.x >> 6);
    int lane = threadIdx.x & 63;

    if (blockIdx.z == 0) {
        if (slot >= g_near_cnt[b]) return;
        float4 q = g_nearc[b*HWN + slot];
        int ix = cell_x(q.x), iy = cell_y(q.y);
        if (ix < 0 || ix >= NXG || iy < 0 || iy >= NYG) return;
        int cell = iy * NXG + ix;
        int p = g_near_idx[b*HWN + slot];
        if (lane == 0) atomicAdd(&g_cnt[b*NCELL + cell], 1.0f);
        float f = g_fvT[((size_t)b*HWN + p) * CC + lane];       // coalesced
        atomicAdd(out + (size_t)b*CC*NCELL + (size_t)lane*NCELL + cell, f);
    } else {
        if (slot >= g_far_cnt[b]) return;
        float4 w = g_fw[b*HWN + slot];
        int4  ii = g_fi[b*HWN + slot];
        const float* fT = g_fvT + (size_t)b*HWN*CC;
        // einsum order: (w0*g0 + w1*g1) + w2*g2, no fma
        float f = __fadd_rn(__fadd_rn(__fmul_rn(w.x, fT[(size_t)ii.x*CC + lane]),
                                      __fmul_rn(w.y, fT[(size_t)ii.y*CC + lane])),
                            __fmul_rn(w.z, fT[(size_t)ii.z*CC + lane]));
        atomicAdd(out + (size_t)b*CC*NCELL + (size_t)lane*NCELL + ii.w, f);
    }
}

// ---------------------------------------------------------------------------
// 5. divide: only cells with cnt >= 2 need a fixup
// ---------------------------------------------------------------------------
__global__ void div_kernel(float* __restrict__ out) {
    int t = blockIdx.x * blockDim.x + threadIdx.x;
    if (t >= BB*NCELL) return;
    float c = g_cnt[t];
    if (c >= 2.0f) {
        int b = t / NCELL, cell = t % NCELL;
        float* ob = out + (size_t)b * CC * NCELL + cell;
        #pragma unroll 8
        for (int ch = 0; ch < CC; ch++)
            ob[(size_t)ch * NCELL] = __fdiv_rn(ob[(size_t)ch * NCELL], c);
    }
}

extern "C" void kernel_launch(void* const* d_in, const int* in_sizes, int n_in,
                              void* d_out, int out_size) {
    const float* fv    = (const float*)d_in[0];   // (B,C,H,W)
    const float* pif   = (const float*)d_in[1];   // (B,4,H,W)
    const int*   mask  = (const int*)  d_in[2];   // (B,H,W)
    const float* piff  = (const float*)d_in[3];   // (B,4,H,W)
    const int*   maskf = (const int*)  d_in[4];   // (B,H,W)
    float* out = (float*)d_out;                   // (B,C,NY,NX)

    void* p_cnt = nullptr;
    cudaGetSymbolAddress(&p_cnt, g_cnt);

    cudaMemsetAsync(d_out, 0, (size_t)BB*CC*NCELL*sizeof(float));
    cudaMemsetAsync(p_cnt, 0, (size_t)BB*NCELL*sizeof(float));

    transpose_kernel<<<dim3(HWN/32, CC/32, BB), dim3(32, 8)>>>(fv);
    compact_kernel<<<BB, 256>>>(pif, mask, piff, maskf);

    knn_kernel<<<dim3(HWN/256, SCH, BB), 256>>>(piff);
    weights_kernel<<<dim3(HWN/256, BB), 256>>>(piff);

    scatter_kernel<<<dim3(HWN/4, BB, 2), 256>>>(out);

    div_kernel<<<(BB*NCELL + 255)/256, 256>>>(out);
}